// round 9
// baseline (speedup 1.0000x reference)
#include <cuda_runtime.h>
#include <cuda_bf16.h>

#define S 128
#define TSTR 132   // smem tile row stride (floats): conflict-free STS + phase-conflict-free LDS.128

__device__ __align__(16) unsigned g_mrow[16 * S * 4];  // bit j: mask[b,i,j]
__device__ __align__(16) unsigned g_span[16 * S * 4];  // bit k: mask[b,j,k] | mask[b,k,j]

__device__ __forceinline__ float sigmoidf_(float x) {
    return 1.0f / (1.0f + __expf(-x));
}
__device__ __forceinline__ unsigned smem_u32(const void* p) {
    unsigned r;
    asm("{ .reg .u64 t; cvta.to.shared.u64 t, %1; cvt.u32.u64 %0, t; }" : "=r"(r) : "l"(p));
    return r;
}
#define CP_ASYNC16(dst, src) \
    asm volatile("cp.async.cg.shared.global [%0], [%1], 16;\n" :: "r"(dst), "l"(src))
#define CP_COMMIT() asm volatile("cp.async.commit_group;\n")
#define CP_WAIT0()  asm volatile("cp.async.wait_group 0;\n")

__device__ __forceinline__ unsigned pick_word(uint4 v, int wd) {
    return (wd == 0) ? v.x : (wd == 1) ? v.y : (wd == 2) ? v.z : v.w;
}

// ---- Pre-kernel: pack masks to bits, one CTA per batch ----
__global__ __launch_bounds__(512)
void mask_pack_kernel(const int* __restrict__ mask) {
    __shared__ unsigned char m[S * 132];
    const int b = blockIdx.x;
    const int t = threadIdx.x;
    const int4* mg = reinterpret_cast<const int4*>(mask + (size_t)b * S * S);
    #pragma unroll
    for (int n = 0; n < 8; n++) {
        int idx = n * 512 + t;
        int row = idx >> 5, c4 = idx & 31;
        int4 v = __ldg(mg + idx);
        uchar4 u;
        u.x = (unsigned char)(v.x != 0); u.y = (unsigned char)(v.y != 0);
        u.z = (unsigned char)(v.z != 0); u.w = (unsigned char)(v.w != 0);
        *reinterpret_cast<uchar4*>(&m[row * 132 + (c4 << 2)]) = u;
    }
    __syncthreads();
    const int w = t >> 5, lane = t & 31;
    for (int task = w; task < 512; task += 16) {
        const int j  = task >> 2;
        const int wd = task & 3;
        const int k  = (wd << 5) + lane;
        unsigned mjk = m[j * 132 + k];
        unsigned mkj = m[k * 132 + j];
        unsigned rw = __ballot_sync(0xffffffffu, mjk != 0);
        unsigned sw = __ballot_sync(0xffffffffu, (mjk | mkj) != 0);
        if (lane == 0) {
            g_mrow[(b * S + j) * 4 + wd] = rw;
            g_span[(b * S + j) * 4 + wd] = sw;
        }
    }
}

// ---- Main: one CTA per (b,i), 256 threads, M in smem, 3 CTAs/SM ----
extern __shared__ float sm[];

__global__ __launch_bounds__(256, 3)
void mfvi_main(const float* __restrict__ s_span,
               const float* __restrict__ s_pair,
               float* __restrict__ out)
{
    float* tile = sm;                // S * TSTR (~67.6 KB)
    float* p    = sm + S * TSTR;     // S
    float* part = p + S;             // S

    const int t    = threadIdx.x;
    const int lane = t & 31;
    const int w    = t >> 5;         // warp 0..7
    const int j    = t & 127;
    const int h    = t >> 7;         // k-half 0..1
    const int kb   = h << 6;

    const int n = blockIdx.x;
    const int b = n >> 7;
    const int i = n & 127;

    const uint4 mr = *reinterpret_cast<const uint4*>(&g_mrow[(b * S + i) * 4]);

    // ---- Producer-aligned loads: this warp loads exactly the strips its threads consume ----
    // warp w covers rows jbase..jbase+31, columns [cb, cb+64)
    {
        const unsigned tb = smem_u32(tile);
        const int jbase = (w & 3) << 5;
        const int cb    = (w >> 2) << 6;         // == kb of this warp's threads
        const int rl    = lane >> 4;             // 0/1: which of 2 rows per instr
        const int co    = (lane & 15) << 2;      // float offset within 64-col segment
        #pragma unroll
        for (int ii = 0; ii < 16; ii++) {
            const int r = jbase + (ii << 1) + rl;
            if ((pick_word(mr, r >> 5) >> (r & 31)) & 1u)
                CP_ASYNC16(tb + (unsigned)((r * TSTR + cb + co) << 2),
                           s_pair + ((size_t)n * S + (size_t)r) * S + cb + co);
        }
        CP_COMMIT();
    }

    // ---- Overlapped with DRAM: p0 init + element-mask words ----
    float ssj = 0.f;
    if (h == 0) {
        ssj = __ldg(&s_span[(size_t)n * S + j]);
        p[j] = sigmoidf_(ssj);
    }
    unsigned em0 = __ldg(&g_span[(b * S + j) * 4 + (h << 1) + 0]);
    unsigned em1 = __ldg(&g_span[(b * S + j) * 4 + (h << 1) + 1]);
    if (!((pick_word(mr, j >> 5) >> (j & 31)) & 1u)) { em0 = 0u; em1 = 0u; }
    {
        const int lo = min(i, j), hi = max(i, j);
        if ((lo >> 5) == (h << 1))     em0 &= ~(1u << (lo & 31));
        if ((lo >> 5) == (h << 1) + 1) em1 &= ~(1u << (lo & 31));
        if ((hi >> 5) == (h << 1))     em0 &= ~(1u << (hi & 31));
        if ((hi >> 5) == (h << 1) + 1) em1 &= ~(1u << (hi & 31));
    }

    __syncthreads();   // p0 visible — placed BEFORE the DRAM wait so it's cheap
    CP_WAIT0();        // warp-local: only this warp's own rows

    // ---- Mask own strip in place (thread-private: no sync needed) ----
    #pragma unroll
    for (int q = 0; q < 16; q++) {
        float4* ptr = reinterpret_cast<float4*>(&tile[j * TSTR + kb + (q << 2)]);
        float4 v = *ptr;
        const unsigned em = (q < 8) ? em0 : em1;
        const int sh = (q << 2) & 31;
        v.x = ((em >> (sh + 0)) & 1u) ? v.x : 0.f;
        v.y = ((em >> (sh + 1)) & 1u) ? v.y : 0.f;
        v.z = ((em >> (sh + 2)) & 1u) ? v.z : 0.f;
        v.w = ((em >> (sh + 3)) & 1u) ? v.w : 0.f;
        *ptr = v;
    }

    // ---- 3 MFVI iterations (M re-read from smem each iter) ----
    #pragma unroll
    for (int it = 0; it < 3; it++) {
        float a0 = 0.f, a1 = 0.f, a2 = 0.f, a3 = 0.f;
        #pragma unroll
        for (int q = 0; q < 16; q++) {
            float4 pv = *reinterpret_cast<const float4*>(&p[kb + (q << 2)]);          // broadcast
            float4 mv = *reinterpret_cast<const float4*>(&tile[j * TSTR + kb + (q << 2)]);
            a0 = fmaf(pv.x, mv.x, a0);
            a1 = fmaf(pv.y, mv.y, a1);
            a2 = fmaf(pv.z, mv.z, a2);
            a3 = fmaf(pv.w, mv.w, a3);
        }
        float acc = (a0 + a1) + (a2 + a3);
        if (h) part[j] = acc;
        __syncthreads();
        if (h == 0) {
            float qv = ssj + acc + part[j];
            if (it < 2) p[j] = sigmoidf_(qv);
            else        out[(size_t)n * S + j] = sigmoidf_(qv);
        }
        if (it < 2) __syncthreads();
    }
}

extern "C" void kernel_launch(void* const* d_in, const int* in_sizes, int n_in,
                              void* d_out, int out_size) {
    const float* s_span = (const float*)d_in[0];
    const float* s_pair = (const float*)d_in[1];
    const int*   mask   = (const int*)d_in[2];
    float* out = (float*)d_out;

    const int smem_bytes = (S * TSTR + 2 * S) * sizeof(float);  // ~68.6 KB
    cudaFuncSetAttribute(mfvi_main, cudaFuncAttributeMaxDynamicSharedMemorySize, smem_bytes);

    mask_pack_kernel<<<16, 512>>>(mask);
    mfvi_main<<<16 * 128, 256, smem_bytes>>>(s_span, s_pair, out);
}

// round 10
// speedup vs baseline: 1.1731x; 1.1731x over previous
#include <cuda_runtime.h>
#include <cuda_bf16.h>

#define S 128
#define TSTR 136   // tile row stride (floats); k>=64 skewed +4 floats (mid-row pad)
#define PS 132     // p buffer stride: slot(j) = j + (j>=64 ? 4 : 0)

__device__ __align__(16) unsigned g_mrow[16 * S * 4];  // bit j: mask[b,i,j]
__device__ __align__(16) unsigned g_span[16 * S * 4];  // bit k: mask[b,j,k] | mask[b,k,j]

__device__ __forceinline__ float sigmoidf_(float x) {
    return 1.0f / (1.0f + __expf(-x));
}
__device__ __forceinline__ unsigned smem_u32(const void* p) {
    unsigned r;
    asm("{ .reg .u64 t; cvta.to.shared.u64 t, %1; cvt.u32.u64 %0, t; }" : "=r"(r) : "l"(p));
    return r;
}
#define CP_ASYNC16(dst, src) \
    asm volatile("cp.async.cg.shared.global [%0], [%1], 16;\n" :: "r"(dst), "l"(src))
#define CP_COMMIT() asm volatile("cp.async.commit_group;\n")
#define CP_WAIT0()  asm volatile("cp.async.wait_group 0;\n")

__device__ __forceinline__ unsigned pick_word(uint4 v, int wd) {
    return (wd == 0) ? v.x : (wd == 1) ? v.y : (wd == 2) ? v.z : v.w;
}

// ---- Pre-kernel: pack masks to bits, one CTA per batch ----
__global__ __launch_bounds__(512)
void mask_pack_kernel(const int* __restrict__ mask) {
    __shared__ unsigned char m[S * 132];
    const int b = blockIdx.x;
    const int t = threadIdx.x;
    const int4* mg = reinterpret_cast<const int4*>(mask + (size_t)b * S * S);
    #pragma unroll
    for (int n = 0; n < 8; n++) {
        int idx = n * 512 + t;
        int row = idx >> 5, c4 = idx & 31;
        int4 v = __ldg(mg + idx);
        uchar4 u;
        u.x = (unsigned char)(v.x != 0); u.y = (unsigned char)(v.y != 0);
        u.z = (unsigned char)(v.z != 0); u.w = (unsigned char)(v.w != 0);
        *reinterpret_cast<uchar4*>(&m[row * 132 + (c4 << 2)]) = u;
    }
    __syncthreads();
    const int w = t >> 5, lane = t & 31;
    for (int task = w; task < 512; task += 16) {
        const int j  = task >> 2;
        const int wd = task & 3;
        const int k  = (wd << 5) + lane;
        unsigned mjk = m[j * 132 + k];
        unsigned mkj = m[k * 132 + j];
        unsigned rw = __ballot_sync(0xffffffffu, mjk != 0);
        unsigned sw = __ballot_sync(0xffffffffu, (mjk | mkj) != 0);
        if (lane == 0) {
            g_mrow[(b * S + j) * 4 + wd] = rw;
            g_span[(b * S + j) * 4 + wd] = sw;
        }
    }
}

// ---- Main: one CTA per (b,i), 256 thr, intra-warp k-split, 3 barriers total ----
extern __shared__ float sm[];

__global__ __launch_bounds__(256, 2)
void mfvi_main(const float* __restrict__ s_span,
               const float* __restrict__ s_pair,
               float* __restrict__ out)
{
    float* tile = sm;                    // S * TSTR (~69.6 KB)
    float* pb0  = sm + S * TSTR;         // PS floats
    float* pb1  = pb0 + PS;              // PS floats

    const int t    = threadIdx.x;
    const int lane = t & 31;
    const int w    = t >> 5;             // warp 0..7
    const int jj   = lane >> 1;          // 0..15
    const int h2   = lane & 1;           // k-half
    const int j    = (w << 4) + jj;
    const int cb   = h2 * 68;            // skewed column base (64 data + 4 pad)

    const int n = blockIdx.x;
    const int b = n >> 7;
    const int i = n & 127;

    const uint4 mr = *reinterpret_cast<const uint4*>(&g_mrow[(b * S + i) * 4]);

    // ---- Producer-aligned loads: warp w loads rows w*16..w*16+15 (full 128 cols) ----
    {
        const unsigned tb = smem_u32(tile);
        const int co   = lane << 2;                      // float col 0..124
        const int dco  = co + ((lane >= 16) ? 4 : 0);    // skewed dst col
        #pragma unroll
        for (int ii = 0; ii < 16; ii++) {
            const int r = (w << 4) + ii;
            if ((pick_word(mr, r >> 5) >> (r & 31)) & 1u)
                CP_ASYNC16(tb + (unsigned)((r * TSTR + dco) << 2),
                           s_pair + ((size_t)n * S + (size_t)r) * S + co);
        }
        CP_COMMIT();
    }

    // ---- Overlapped with DRAM: scalars, em words, p0 init ----
    float ssj = 0.f;
    if (h2 == 0) ssj = __ldg(&s_span[(size_t)n * S + j]);
    unsigned em0 = __ldg(&g_span[(b * S + j) * 4 + (h2 << 1) + 0]);
    unsigned em1 = __ldg(&g_span[(b * S + j) * 4 + (h2 << 1) + 1]);
    if (!((pick_word(mr, j >> 5) >> (j & 31)) & 1u)) { em0 = 0u; em1 = 0u; }
    {
        const int lo = min(i, j), hi = max(i, j);
        if ((lo >> 5) == (h2 << 1))     em0 &= ~(1u << (lo & 31));
        if ((lo >> 5) == (h2 << 1) + 1) em1 &= ~(1u << (lo & 31));
        if ((hi >> 5) == (h2 << 1))     em0 &= ~(1u << (hi & 31));
        if ((hi >> 5) == (h2 << 1) + 1) em1 &= ~(1u << (hi & 31));
    }
    if (t < S) {
        float v = __ldg(&s_span[(size_t)n * S + t]);
        pb0[t + ((t >= 64) ? 4 : 0)] = sigmoidf_(v);
    }

    __syncthreads();   // bar 1: p0 visible (cheap — before the DRAM wait)
    CP_WAIT0();        // warp-local: only this warp's own rows

    // ---- Pull masked 64-float k-half strip into registers (conflict-free LDS.128) ----
    float M[64];
    #pragma unroll
    for (int q = 0; q < 16; q++) {
        float4 v = *reinterpret_cast<const float4*>(&tile[j * TSTR + cb + (q << 2)]);
        const unsigned em = (q < 8) ? em0 : em1;
        const int sh = (q << 2) & 31;
        M[4*q+0] = ((em >> (sh + 0)) & 1u) ? v.x : 0.f;
        M[4*q+1] = ((em >> (sh + 1)) & 1u) ? v.y : 0.f;
        M[4*q+2] = ((em >> (sh + 2)) & 1u) ? v.z : 0.f;
        M[4*q+3] = ((em >> (sh + 3)) & 1u) ? v.w : 0.f;
    }

    // ---- 3 MFVI iterations: shfl-reduce, double-buffered p, 1 bar/iter ----
    #pragma unroll
    for (int it = 0; it < 3; it++) {
        const float* pr = (it & 1) ? pb1 : pb0;
        float*       pw = (it & 1) ? pb0 : pb1;
        float a0 = 0.f, a1 = 0.f, a2 = 0.f, a3 = 0.f;
        #pragma unroll
        for (int q = 0; q < 16; q++) {
            float4 pv = *reinterpret_cast<const float4*>(&pr[cb + (q << 2)]);
            a0 = fmaf(pv.x, M[4*q+0], a0);
            a1 = fmaf(pv.y, M[4*q+1], a1);
            a2 = fmaf(pv.z, M[4*q+2], a2);
            a3 = fmaf(pv.w, M[4*q+3], a3);
        }
        float acc = (a0 + a1) + (a2 + a3);
        acc += __shfl_xor_sync(0xffffffffu, acc, 1);   // combine the two k-halves
        if (it < 2) {
            if (h2 == 0)
                pw[j + ((j >= 64) ? 4 : 0)] = sigmoidf_(ssj + acc);
            __syncthreads();                            // bars 2,3
        } else {
            if (h2 == 0)
                out[(size_t)n * S + j] = sigmoidf_(ssj + acc);
        }
    }
}

extern "C" void kernel_launch(void* const* d_in, const int* in_sizes, int n_in,
                              void* d_out, int out_size) {
    const float* s_span = (const float*)d_in[0];
    const float* s_pair = (const float*)d_in[1];
    const int*   mask   = (const int*)d_in[2];
    float* out = (float*)d_out;

    const int smem_bytes = (S * TSTR + 2 * PS) * sizeof(float);  // ~70.7 KB
    cudaFuncSetAttribute(mfvi_main, cudaFuncAttributeMaxDynamicSharedMemorySize, smem_bytes);

    mask_pack_kernel<<<16, 512>>>(mask);
    mfvi_main<<<16 * 128, 256, smem_bytes>>>(s_span, s_pair, out);
}

// round 11
// speedup vs baseline: 1.3147x; 1.1207x over previous
#include <cuda_runtime.h>
#include <cuda_bf16.h>

#define S 128
#define TSTR 136   // tile row stride (floats); k>=64 skewed +4 floats (mid-row pad)
#define PS 132     // p buffer stride: slot(j) = j + (j>=64 ? 4 : 0)
#define NCTA 296   // persistent: 2 CTAs per SM
#define NTILE 2048

__device__ __align__(16) unsigned g_mrow[16 * S * 4];  // bit j: mask[b,i,j]
__device__ __align__(16) unsigned g_span[16 * S * 4];  // bit k: mask[b,j,k] | mask[b,k,j]

__device__ __forceinline__ float sigmoidf_(float x) {
    return 1.0f / (1.0f + __expf(-x));
}
__device__ __forceinline__ unsigned smem_u32(const void* p) {
    unsigned r;
    asm("{ .reg .u64 t; cvta.to.shared.u64 t, %1; cvt.u32.u64 %0, t; }" : "=r"(r) : "l"(p));
    return r;
}
#define CP_ASYNC16(dst, src) \
    asm volatile("cp.async.cg.shared.global [%0], [%1], 16;\n" :: "r"(dst), "l"(src))
#define CP_COMMIT() asm volatile("cp.async.commit_group;\n")
#define CP_WAIT0()  asm volatile("cp.async.wait_group 0;\n")

__device__ __forceinline__ unsigned pick_word(uint4 v, int wd) {
    return (wd == 0) ? v.x : (wd == 1) ? v.y : (wd == 2) ? v.z : v.w;
}

// ---- Pre-kernel: pack masks to bits; grid (16 batches x 4 j-quarters) ----
__global__ __launch_bounds__(512)
void mask_pack_kernel(const int* __restrict__ mask) {
    __shared__ unsigned char m[S * 132];
    const int b  = blockIdx.x;
    const int qy = blockIdx.y;
    const int t  = threadIdx.x;
    const int4* mg = reinterpret_cast<const int4*>(mask + (size_t)b * S * S);
    #pragma unroll
    for (int n = 0; n < 8; n++) {
        int idx = n * 512 + t;
        int row = idx >> 5, c4 = idx & 31;
        int4 v = __ldg(mg + idx);
        uchar4 u;
        u.x = (unsigned char)(v.x != 0); u.y = (unsigned char)(v.y != 0);
        u.z = (unsigned char)(v.z != 0); u.w = (unsigned char)(v.w != 0);
        *reinterpret_cast<uchar4*>(&m[row * 132 + (c4 << 2)]) = u;
    }
    __syncthreads();
    const int w = t >> 5, lane = t & 31;
    for (int task = w; task < 128; task += 16) {      // 32 j x 4 words
        const int j  = (qy << 5) + (task >> 2);
        const int wd = task & 3;
        const int k  = (wd << 5) + lane;
        unsigned mjk = m[j * 132 + k];
        unsigned mkj = m[k * 132 + j];
        unsigned rw = __ballot_sync(0xffffffffu, mjk != 0);
        unsigned sw = __ballot_sync(0xffffffffu, (mjk | mkj) != 0);
        if (lane == 0) {
            g_mrow[(b * S + j) * 4 + wd] = rw;
            g_span[(b * S + j) * 4 + wd] = sw;
        }
    }
}

// ---- Main: persistent CTAs, warp-local smem-reuse pipeline ----
extern __shared__ float sm[];

__global__ __launch_bounds__(256, 2)
void mfvi_main(const float* __restrict__ s_span,
               const float* __restrict__ s_pair,
               float* __restrict__ out)
{
    float* tile = sm;                    // S * TSTR (~69.6 KB), single buffer
    float* pb0  = sm + S * TSTR;         // PS
    float* pb1  = pb0 + PS;              // PS

    const int t    = threadIdx.x;
    const int lane = t & 31;
    const int w    = t >> 5;             // warp 0..7
    const int jj   = lane >> 1;
    const int h2   = lane & 1;           // k-half
    const int j    = (w << 4) + jj;
    const int cb   = h2 * 68;            // skewed column base

    const unsigned tb  = smem_u32(tile);
    const int co   = lane << 2;                      // src float col
    const int dco  = co + ((lane >= 16) ? 4 : 0);    // skewed dst col

    // ---- prologue: issue first tile's loads (warp-local rows) ----
    int n = blockIdx.x;
    uint4 mr = *reinterpret_cast<const uint4*>(&g_mrow[((n >> 7) * S + (n & 127)) * 4]);
    #pragma unroll
    for (int ii = 0; ii < 16; ii++) {
        const int r = (w << 4) + ii;
        if ((pick_word(mr, r >> 5) >> (r & 31)) & 1u)
            CP_ASYNC16(tb + (unsigned)((r * TSTR + dco) << 2),
                       s_pair + ((size_t)n * S + (size_t)r) * S + co);
    }
    CP_COMMIT();

    for (; n < NTILE; n += NCTA) {
        const int b = n >> 7;
        const int i = n & 127;

        // ---- scalars + em words + p0 init (overlaps current tile's DRAM) ----
        float ssj = 0.f;
        if (h2 == 0) ssj = __ldg(&s_span[(size_t)n * S + j]);
        unsigned em0 = __ldg(&g_span[(b * S + j) * 4 + (h2 << 1) + 0]);
        unsigned em1 = __ldg(&g_span[(b * S + j) * 4 + (h2 << 1) + 1]);
        if (!((pick_word(mr, j >> 5) >> (j & 31)) & 1u)) { em0 = 0u; em1 = 0u; }
        {
            const int lo = min(i, j), hi = max(i, j);
            if ((lo >> 5) == (h2 << 1))     em0 &= ~(1u << (lo & 31));
            if ((lo >> 5) == (h2 << 1) + 1) em1 &= ~(1u << (lo & 31));
            if ((hi >> 5) == (h2 << 1))     em0 &= ~(1u << (hi & 31));
            if ((hi >> 5) == (h2 << 1) + 1) em1 &= ~(1u << (hi & 31));
        }
        if (t < S) {
            float v = __ldg(&s_span[(size_t)n * S + t]);
            pb0[t + ((t >= 64) ? 4 : 0)] = sigmoidf_(v);
        }
        // prefetch next tile's row-mask (for the post-readback issue)
        const int nn = n + NCTA;
        uint4 mr_next = make_uint4(0u, 0u, 0u, 0u);
        if (nn < NTILE)
            mr_next = *reinterpret_cast<const uint4*>(
                &g_mrow[((nn >> 7) * S + (nn & 127)) * 4]);

        __syncthreads();   // bar1: p0 visible; pb0/pb1 safe (bar4 of prev tile)

        CP_WAIT0();        // current tile's rows landed (only group in flight)

        // ---- readback + mask into registers (warp-local rows) ----
        float M[64];
        #pragma unroll
        for (int q = 0; q < 16; q++) {
            float4 v = *reinterpret_cast<const float4*>(&tile[j * TSTR + cb + (q << 2)]);
            const unsigned em = (q < 8) ? em0 : em1;
            const int sh = (q << 2) & 31;
            M[4*q+0] = ((em >> (sh + 0)) & 1u) ? v.x : 0.f;
            M[4*q+1] = ((em >> (sh + 1)) & 1u) ? v.y : 0.f;
            M[4*q+2] = ((em >> (sh + 2)) & 1u) ? v.z : 0.f;
            M[4*q+3] = ((em >> (sh + 3)) & 1u) ? v.w : 0.f;
        }

        // ---- issue NEXT tile's loads into the same rows (warp-local, no barrier) ----
        if (nn < NTILE) {
            #pragma unroll
            for (int ii = 0; ii < 16; ii++) {
                const int r = (w << 4) + ii;
                if ((pick_word(mr_next, r >> 5) >> (r & 31)) & 1u)
                    CP_ASYNC16(tb + (unsigned)((r * TSTR + dco) << 2),
                               s_pair + ((size_t)nn * S + (size_t)r) * S + co);
            }
            CP_COMMIT();
        }
        mr = mr_next;

        // ---- 3 MFVI iterations (DRAM for next tile lands underneath) ----
        #pragma unroll
        for (int it = 0; it < 3; it++) {
            const float* pr = (it & 1) ? pb1 : pb0;
            float*       pw = (it & 1) ? pb0 : pb1;
            float a0 = 0.f, a1 = 0.f, a2 = 0.f, a3 = 0.f;
            #pragma unroll
            for (int q = 0; q < 16; q++) {
                float4 pv = *reinterpret_cast<const float4*>(&pr[cb + (q << 2)]);
                a0 = fmaf(pv.x, M[4*q+0], a0);
                a1 = fmaf(pv.y, M[4*q+1], a1);
                a2 = fmaf(pv.z, M[4*q+2], a2);
                a3 = fmaf(pv.w, M[4*q+3], a3);
            }
            float acc = (a0 + a1) + (a2 + a3);
            acc += __shfl_xor_sync(0xffffffffu, acc, 1);
            if (it < 2) {
                if (h2 == 0)
                    pw[j + ((j >= 64) ? 4 : 0)] = sigmoidf_(ssj + acc);
                __syncthreads();                       // bars 2,3
            } else {
                if (h2 == 0)
                    out[(size_t)n * S + j] = sigmoidf_(ssj + acc);
                __syncthreads();                       // bar4: pb0/pb1 reuse guard
            }
        }
    }
}

extern "C" void kernel_launch(void* const* d_in, const int* in_sizes, int n_in,
                              void* d_out, int out_size) {
    const float* s_span = (const float*)d_in[0];
    const float* s_pair = (const float*)d_in[1];
    const int*   mask   = (const int*)d_in[2];
    float* out = (float*)d_out;

    const int smem_bytes = (S * TSTR + 2 * PS) * sizeof(float);  // ~70.7 KB
    cudaFuncSetAttribute(mfvi_main, cudaFuncAttributeMaxDynamicSharedMemorySize, smem_bytes);

    dim3 pg(16, 4);
    mask_pack_kernel<<<pg, 512>>>(mask);
    mfvi_main<<<NCTA, 256, smem_bytes>>>(s_span, s_pair, out);
}